// round 16
// baseline (speedup 1.0000x reference)
#include <cuda_runtime.h>
#include <cstdint>
#include <cstddef>

#define BN 32
#define NT 256
#define DD 2048
#define KC 64
#define BIGF 1e30f

// ---------------- scratch (static device globals; no allocation) ----------------
__device__ float g_rinv[BN * NT];
__device__ float g_S[BN * NT * NT];              // 8.4 MB
__device__ float g_Dm[BN * NT * NT];             // 8.4 MB
__device__ float g_part[4][BN * NT * NT];        // 33.6 MB split-K partials
__device__ float g_sq[BN * NT];
__device__ float g_salmass[BN * NT];
__device__ float g_minv0[BN * NT];
__device__ int   g_mini0[BN * NT];
__device__ int   g_order[BN * NT];
__device__ int   g_ccnt[BN * KC];
__device__ int   g_coff[BN * KC];
__device__ float g_maskdump[BN * NT];

// ---------------- 1: reciprocal row norms ----------------
__global__ void rnorm_kernel(const float* __restrict__ X) {
    int row = blockIdx.x * 8 + (threadIdx.x >> 5);
    int lane = threadIdx.x & 31;
    const float* x = X + (size_t)row * DD;
    float s = 0.f;
    for (int c = lane * 4; c < DD; c += 128) {
        float4 v = *(const float4*)&x[c];
        s += v.x * v.x + v.y * v.y + v.z * v.z + v.w * v.w;
    }
    #pragma unroll
    for (int o = 16; o; o >>= 1) s += __shfl_down_sync(0xffffffffu, s, o);
    if (lane == 0) g_rinv[row] = 1.0f / fmaxf(sqrtf(s), 1e-12f);
}

__global__ void dummy_kernel() {}

// ---------------- 2: split-K fp32 GEMM with packed f32x2 FMA (proven 256-thread) ----------------
template <int MODE, int SPLIT>
__global__ __launch_bounds__(256, 2) void gemm128(const float* __restrict__ Ain) {
    constexpr int LD = (MODE == 0) ? DD : NT;
    constexpr int KP = LD / SPLIT;
    int b = blockIdx.y;
    int t3 = blockIdx.x;
    int tr = (t3 == 2) ? 1 : 0;
    int tc = (t3 == 0) ? 0 : 1;
    int koff = blockIdx.z * KP;
    const float* A = ((MODE == 0) ? Ain : g_S) + (size_t)b * NT * LD;
    float* P = g_part[blockIdx.z] + (size_t)b * NT * NT;

    __shared__ __align__(16) float As[2][8][132];
    __shared__ __align__(16) float Bs[2][8][132];

    int tid = threadIdx.x;
    int frow = tid & 127;
    int fk = (tid >> 7) * 4;
    int g = tid & 15;
    int h = tid >> 4;

    float sa = 1.f, sb = 1.f;
    if (MODE == 0) {
        sa = g_rinv[b * NT + tr * 128 + frow];
        sb = g_rinv[b * NT + tc * 128 + frow];
    }

    unsigned long long accd[8][4];
    #pragma unroll
    for (int i = 0; i < 8; i++)
        #pragma unroll
        for (int jp = 0; jp < 4; jp++) accd[i][jp] = 0ULL;

    const float* Ag = A + (size_t)(tr * 128 + frow) * LD + koff;
    const float* Bg = A + (size_t)(tc * 128 + frow) * LD + koff;

    {
        float4 fa = *(const float4*)(Ag + fk);
        float4 fb = *(const float4*)(Bg + fk);
        if (MODE == 0) {
            fa.x *= sa; fa.y *= sa; fa.z *= sa; fa.w *= sa;
            fb.x *= sb; fb.y *= sb; fb.z *= sb; fb.w *= sb;
        }
        As[0][fk + 0][frow] = fa.x; As[0][fk + 1][frow] = fa.y;
        As[0][fk + 2][frow] = fa.z; As[0][fk + 3][frow] = fa.w;
        Bs[0][fk + 0][frow] = fb.x; Bs[0][fk + 1][frow] = fb.y;
        Bs[0][fk + 2][frow] = fb.z; Bs[0][fk + 3][frow] = fb.w;
    }
    __syncthreads();

    int cur = 0;
    for (int k0 = 8; k0 < KP + 8; k0 += 8) {
        bool has = (k0 < KP);
        float4 na, nb;
        if (has) {
            na = *(const float4*)(Ag + k0 + fk);
            nb = *(const float4*)(Bg + k0 + fk);
            if (MODE == 0) {
                na.x *= sa; na.y *= sa; na.z *= sa; na.w *= sa;
                nb.x *= sb; nb.y *= sb; nb.z *= sb; nb.w *= sb;
            }
        }
        #pragma unroll
        for (int kk = 0; kk < 8; kk++) {
            float a4[8];
            *(float4*)&a4[0] = *(const float4*)&As[cur][kk][g * 4];
            *(float4*)&a4[4] = *(const float4*)&As[cur][kk][64 + g * 4];
            ulonglong2 b01 = *(const ulonglong2*)&Bs[cur][kk][h * 4];
            ulonglong2 b23 = *(const ulonglong2*)&Bs[cur][kk][64 + h * 4];
            unsigned long long bq0 = b01.x, bq1 = b01.y, bq2 = b23.x, bq3 = b23.y;
            #pragma unroll
            for (int i = 0; i < 8; i++) {
                unsigned int au = __float_as_uint(a4[i]);
                unsigned long long ad;
                asm("mov.b64 %0, {%1, %1};" : "=l"(ad) : "r"(au));
                asm("fma.rn.f32x2 %0, %1, %2, %0;" : "+l"(accd[i][0]) : "l"(ad), "l"(bq0));
                asm("fma.rn.f32x2 %0, %1, %2, %0;" : "+l"(accd[i][1]) : "l"(ad), "l"(bq1));
                asm("fma.rn.f32x2 %0, %1, %2, %0;" : "+l"(accd[i][2]) : "l"(ad), "l"(bq2));
                asm("fma.rn.f32x2 %0, %1, %2, %0;" : "+l"(accd[i][3]) : "l"(ad), "l"(bq3));
            }
        }
        if (has) {
            int alt = cur ^ 1;
            As[alt][fk + 0][frow] = na.x; As[alt][fk + 1][frow] = na.y;
            As[alt][fk + 2][frow] = na.z; As[alt][fk + 3][frow] = na.w;
            Bs[alt][fk + 0][frow] = nb.x; Bs[alt][fk + 1][frow] = nb.y;
            Bs[alt][fk + 2][frow] = nb.z; Bs[alt][fk + 3][frow] = nb.w;
            __syncthreads();
            cur = alt;
        }
    }

    int r0 = tr * 128, c0 = tc * 128;
    #pragma unroll
    for (int i = 0; i < 8; i++) {
        int r = r0 + ((i < 4) ? (g * 4 + i) : (64 + g * 4 + i - 4));
        float vv[8];
        #pragma unroll
        for (int jp = 0; jp < 4; jp++) {
            unsigned int lo, hi;
            asm("mov.b64 {%0, %1}, %2;" : "=r"(lo), "=r"(hi) : "l"(accd[i][jp]));
            vv[2 * jp]     = __uint_as_float(lo);
            vv[2 * jp + 1] = __uint_as_float(hi);
        }
        float4 v0 = {vv[0], vv[1], vv[2], vv[3]};
        float4 v1 = {vv[4], vv[5], vv[6], vv[7]};
        *(float4*)&P[r * NT + c0 + h * 4] = v0;
        *(float4*)&P[r * NT + c0 + 64 + h * 4] = v1;
        if (tr != tc) {
            #pragma unroll
            for (int j = 0; j < 4; j++) P[(c0 + h * 4 + j) * NT + r] = vv[j];
            #pragma unroll
            for (int j = 0; j < 4; j++) P[(c0 + 64 + h * 4 + j) * NT + r] = vv[4 + j];
        }
    }
}

// ---------------- combine0 + fused row sums of squares ----------------
__global__ __launch_bounds__(256) void combine0_kernel() {
    int tid = threadIdx.x;
    int idx = blockIdx.x * 256 + tid;
    const float4* p0 = (const float4*)g_part[0];
    const float4* p1 = (const float4*)g_part[1];
    const float4* p2 = (const float4*)g_part[2];
    const float4* p3 = (const float4*)g_part[3];
    float4 a = p0[idx], b = p1[idx], c = p2[idx], d = p3[idx];
    float4 o;
    o.x = ((a.x + b.x) + c.x) + d.x;
    o.y = ((a.y + b.y) + c.y) + d.y;
    o.z = ((a.z + b.z) + c.z) + d.z;
    o.w = ((a.w + b.w) + c.w) + d.w;
    ((float4*)g_S)[idx] = o;

    float s = o.x * o.x + o.y * o.y + o.z * o.z + o.w * o.w;
    #pragma unroll
    for (int off = 16; off; off >>= 1) s += __shfl_down_sync(0xffffffffu, s, off);
    __shared__ float sws[8];
    int wid = tid >> 5;
    if ((tid & 31) == 0) sws[wid] = s;
    __syncthreads();
    if (tid < 4) g_sq[blockIdx.x * 4 + tid] = sws[2 * tid] + sws[2 * tid + 1];
}

// Dm full-square write + per-row initial nearest neighbor (min, argmin)
__global__ __launch_bounds__(256) void combine1_kernel() {
    int tid = threadIdx.x;
    int idx = blockIdx.x * 256 + tid;
    int c4 = idx & 63;
    int r = (idx >> 6) & 255;
    int b = idx >> 14;
    const float4* p0 = (const float4*)g_part[0];
    const float4* p1 = (const float4*)g_part[1];
    float4 t0 = p0[idx], t1 = p1[idx];
    float sqr = g_sq[b * NT + r];
    float4 sqc = ((const float4*)(g_sq + b * NT))[c4];
    float4 o;
    o.x = sqrtf(fmaxf(sqr + sqc.x - 2.f * (t0.x + t1.x), 0.f));
    o.y = sqrtf(fmaxf(sqr + sqc.y - 2.f * (t0.y + t1.y), 0.f));
    o.z = sqrtf(fmaxf(sqr + sqc.z - 2.f * (t0.z + t1.z), 0.f));
    o.w = sqrtf(fmaxf(sqr + sqc.w - 2.f * (t0.w + t1.w), 0.f));
    int cb = c4 * 4;
    if (r == cb + 0) o.x = BIGF;
    if (r == cb + 1) o.y = BIGF;
    if (r == cb + 2) o.z = BIGF;
    if (r == cb + 3) o.w = BIGF;
    ((float4*)g_Dm)[idx] = o;

    float v = o.x; int ci = cb;
    if (o.y < v) { v = o.y; ci = cb + 1; }
    if (o.z < v) { v = o.z; ci = cb + 2; }
    if (o.w < v) { v = o.w; ci = cb + 3; }
    unsigned uv = __reduce_min_sync(0xffffffffu, __float_as_uint(v));
    unsigned cand = (__float_as_uint(v) == uv) ? (unsigned)ci : 0x7FFFFFFFu;
    unsigned wmin = __reduce_min_sync(0xffffffffu, cand);
    __shared__ float swv[8];
    __shared__ int   swi[8];
    int wid = tid >> 5;
    if ((tid & 31) == 0) { swv[wid] = __uint_as_float(uv); swi[wid] = (int)wmin; }
    __syncthreads();
    if (tid < 4) {
        float bv = swv[2 * tid]; int bi = swi[2 * tid];
        float v1 = swv[2 * tid + 1]; int i1 = swi[2 * tid + 1];
        if (v1 < bv || (v1 == bv && i1 < bi)) { bv = v1; bi = i1; }
        int flat_row = blockIdx.x * 4 + tid;
        g_minv0[flat_row] = bv;
        g_mini0[flat_row] = bi;
    }
}

// ---------------- 4: clustering v8 — two batches per block via named barriers ----------------
#define GBAR() asm volatile("bar.sync %0, 256;" :: "r"(grp + 1) : "memory")

__device__ __forceinline__ void row_scan4m(const float* __restrict__ row,
                                           const unsigned int* __restrict__ actw,
                                           int lane, float& bv, int& bi) {
    const float4* r4 = (const float4*)row;
    float4 f0 = r4[lane];
    float4 f1 = r4[lane + 32];
    unsigned int w0 = actw[lane >> 3] >> ((4 * lane) & 31);
    unsigned int w1 = actw[(lane >> 3) + 4] >> ((4 * lane) & 31);
    float v = BIGF; int idx = 1 << 20;
    if ((w0 & 1u) && f0.x < v) { v = f0.x; idx = 4 * lane; }
    if ((w0 & 2u) && f0.y < v) { v = f0.y; idx = 4 * lane + 1; }
    if ((w0 & 4u) && f0.z < v) { v = f0.z; idx = 4 * lane + 2; }
    if ((w0 & 8u) && f0.w < v) { v = f0.w; idx = 4 * lane + 3; }
    if ((w1 & 1u) && f1.x < v) { v = f1.x; idx = 128 + 4 * lane; }
    if ((w1 & 2u) && f1.y < v) { v = f1.y; idx = 128 + 4 * lane + 1; }
    if ((w1 & 4u) && f1.z < v) { v = f1.z; idx = 128 + 4 * lane + 2; }
    if ((w1 & 8u) && f1.w < v) { v = f1.w; idx = 128 + 4 * lane + 3; }
    unsigned uv = __reduce_min_sync(0xffffffffu, __float_as_uint(v));
    unsigned cand = (__float_as_uint(v) == uv) ? (unsigned)idx : 0x7FFFFFFFu;
    bi = (int)__reduce_min_sync(0xffffffffu, cand);
    bv = __uint_as_float(uv);
}

__global__ __launch_bounds__(512) void cluster_kernel() {
    const int grp = threadIdx.x >> 8;               // 0 or 1
    const int t = threadIdx.x & 255;
    const int b = blockIdx.x * 2 + grp;
    float* Dm = g_Dm + (size_t)b * NT * NT;
    const int lane = t & 31, wid = t >> 5;          // wid 0..7 within group

    __shared__ __align__(16) float s_minv[2][2][NT];   // [grp][buf][row]
    __shared__ short s_mini[2][NT];
    __shared__ float s_size[2][NT];
    __shared__ unsigned char s_active[2][NT];
    __shared__ unsigned int s_actw[2][8];
    __shared__ short s_label[2][NT];
    __shared__ float s_wv[2][8];
    __shared__ int   s_wi[2][8];
    __shared__ int   s_recount[2][2];
    __shared__ short s_relist[2][2][NT];

    s_active[grp][t] = 1; s_size[grp][t] = 1.f; s_label[grp][t] = (short)t;
    s_minv[grp][0][t] = g_minv0[b * NT + t];
    s_mini[grp][t] = (short)g_mini0[b * NT + t];
    if (t < 8) s_actw[grp][t] = 0xFFFFFFFFu;
    if (t < 2) s_recount[grp][t] = 0;
    GBAR();

    int cur = 0;
    for (int it = 0; it < NT - KC; ++it) {
        int nxt = cur ^ 1;
        // ---- phase 1 ----
        int i;
        {
            const float4* m4 = (const float4*)s_minv[grp][cur];
            float4 f0 = m4[lane];
            float4 f1 = m4[lane + 32];
            float v = f0.x; int idx = 4 * lane;
            if (f0.y < v) { v = f0.y; idx = 4 * lane + 1; }
            if (f0.z < v) { v = f0.z; idx = 4 * lane + 2; }
            if (f0.w < v) { v = f0.w; idx = 4 * lane + 3; }
            if (f1.x < v) { v = f1.x; idx = 128 + 4 * lane; }
            if (f1.y < v) { v = f1.y; idx = 128 + 4 * lane + 1; }
            if (f1.z < v) { v = f1.z; idx = 128 + 4 * lane + 2; }
            if (f1.w < v) { v = f1.w; idx = 128 + 4 * lane + 3; }
            unsigned uv = __reduce_min_sync(0xffffffffu, __float_as_uint(v));
            unsigned cand = (__float_as_uint(v) == uv) ? (unsigned)idx : 0x7FFFFFFFu;
            i = (int)__reduce_min_sync(0xffffffffu, cand);
        }
        int j = s_mini[grp][i];
        float si = s_size[grp][i], sj = s_size[grp][j];
        bool act = (s_active[grp][t] != 0);
        float nv = BIGF;
        if (act && t != j) {
            float di = Dm[(size_t)i * NT + t];
            float dj = Dm[(size_t)j * NT + t];
            nv = (si * di + sj * dj) / (si + sj);
            if (t == i) nv = BIGF;
            Dm[(size_t)i * NT + t] = nv;
            Dm[(size_t)t * NT + i] = nv;
        }
        if (t == j) {
            s_active[grp][j] = 0;
            s_actw[grp][j >> 5] &= ~(1u << (j & 31));
        }
        if (s_label[grp][t] == (short)j) s_label[grp][t] = (short)i;

        // row i's new rowmin candidate from nv (REDUX lexicographic)
        {
            float cv = (act && t != i && t != j) ? nv : BIGF;
            unsigned uv2 = __reduce_min_sync(0xffffffffu, __float_as_uint(cv));
            unsigned cc = (__float_as_uint(cv) == uv2) ? (unsigned)t : 0x7FFFFFFFu;
            unsigned wmin = __reduce_min_sync(0xffffffffu, cc);
            if (lane == 0) { s_wv[grp][wid] = __uint_as_float(uv2); s_wi[grp][wid] = (int)wmin; }
        }

        // maintenance + copy-forward
        float nmv;
        if (!act || t == i || t == j) {
            nmv = BIGF;
        } else {
            float mv = s_minv[grp][cur][t]; int mi = s_mini[grp][t];
            if (mi == i || mi == j) {
                if (nv < mv) { nmv = nv; s_mini[grp][t] = (short)i; }
                else { nmv = mv; int p = atomicAdd(&s_recount[grp][cur], 1); s_relist[grp][cur][p] = (short)t; }
            } else if (nv < mv || (nv == mv && i < mi)) {
                nmv = nv; s_mini[grp][t] = (short)i;
            } else nmv = mv;
        }
        s_minv[grp][nxt][t] = nmv;
        GBAR();                                   // (B)

        // ---- phase 2 ----
        if (t == 0) {
            float bv = s_wv[grp][0]; int bi2 = s_wi[grp][0];
            #pragma unroll
            for (int w = 1; w < 8; w++)
                if (s_wv[grp][w] < bv || (s_wv[grp][w] == bv && s_wi[grp][w] < bi2)) { bv = s_wv[grp][w]; bi2 = s_wi[grp][w]; }
            s_minv[grp][nxt][i] = bv; s_mini[grp][i] = (short)bi2;
            s_size[grp][i] = si + sj;
            s_recount[grp][nxt] = 0;
        }
        int rc = s_recount[grp][cur];
        for (int e = wid; e < rc; e += 8) {
            int r2 = s_relist[grp][cur][e];
            float v2; int i2;
            row_scan4m(Dm + (size_t)r2 * NT, s_actw[grp], lane, v2, i2);
            if (lane == 0) { s_minv[grp][nxt][r2] = v2; s_mini[grp][r2] = (short)i2; }
        }
        GBAR();                                   // (C)
        cur = nxt;
    }

    // canonical relabel: new_id = cumsum(active)-1
    __shared__ short s_newid[2][NT];
    __shared__ short s_flab[2][NT];
    __shared__ short s_cnt[2][KC];
    __shared__ short s_off[2][KC];
    {
        int c = 0;
        for (int r2 = 0; r2 <= t; ++r2) c += s_active[grp][r2];
        s_newid[grp][t] = (short)(c - 1);
    }
    GBAR();
    int fl = s_newid[grp][s_label[grp][t]];
    s_flab[grp][t] = (short)fl;
    GBAR();
    if (t < KC) {
        int cnt = 0;
        for (int r2 = 0; r2 < NT; r2++) cnt += (s_flab[grp][r2] == (short)t);
        s_cnt[grp][t] = (short)cnt;
        g_ccnt[b * KC + t] = cnt;
    }
    GBAR();
    if (t < KC) {
        int off = 0;
        for (int k2 = 0; k2 < t; k2++) off += s_cnt[grp][k2];
        s_off[grp][t] = (short)off;
        g_coff[b * KC + t] = off;
    }
    GBAR();
    {
        int rank = 0;
        for (int r2 = 0; r2 < t; r2++) rank += (s_flab[grp][r2] == (short)fl);
        g_order[b * NT + s_off[grp][fl] + rank] = t;
    }
}

// ---------------- 5: mask (softmax) + sal_mass ----------------
__global__ void mask_kernel(const float* __restrict__ sal,
                            const float* __restrict__ gum,
                            float* __restrict__ mout) {
    int b = blockIdx.x, t = threadIdx.x;
    float s = sal[b * NT + t];
    float l = (s + gum[b * NT + t]) / 0.1f;
    __shared__ float red[8];
    float m = l;
    #pragma unroll
    for (int o = 16; o; o >>= 1) m = fmaxf(m, __shfl_xor_sync(0xffffffffu, m, o));
    if ((t & 31) == 0) red[t >> 5] = m;
    __syncthreads();
    float mx = red[0];
    #pragma unroll
    for (int w = 1; w < 8; w++) mx = fmaxf(mx, red[w]);
    float e = expf(l - mx);
    float sm = e;
    #pragma unroll
    for (int o = 16; o; o >>= 1) sm += __shfl_xor_sync(0xffffffffu, sm, o);
    __syncthreads();
    if ((t & 31) == 0) red[t >> 5] = sm;
    __syncthreads();
    float tot = 0.f;
    #pragma unroll
    for (int w = 0; w < 8; w++) tot += red[w];
    float mk = e / tot;
    mout[b * NT + t] = mk;
    g_salmass[b * NT + t] = mk * s + (1.f - mk) * 0.01f;
}

// ---------------- 6: saliency-weighted per-cluster merge ----------------
__global__ __launch_bounds__(256) void merge_kernel(const float* __restrict__ X,
                                                    float* __restrict__ out) {
    int b = blockIdx.x >> 6;
    int k = blockIdx.x & 63;
    int cnt = g_ccnt[b * KC + k];
    int off = g_coff[b * KC + k];
    int t = threadIdx.x;
    int d0 = t * 8;
    float acc[8] = {0.f, 0.f, 0.f, 0.f, 0.f, 0.f, 0.f, 0.f};
    float den = 0.f;
    for (int e = 0; e < cnt; ++e) {
        int tok = g_order[b * NT + off + e];
        float w = g_salmass[b * NT + tok];
        den += w;
        const float4* xp = (const float4*)(X + ((size_t)(b * NT + tok) * DD + d0));
        float4 x0 = xp[0], x1 = xp[1];
        acc[0] += w * x0.x; acc[1] += w * x0.y; acc[2] += w * x0.z; acc[3] += w * x0.w;
        acc[4] += w * x1.x; acc[5] += w * x1.y; acc[6] += w * x1.z; acc[7] += w * x1.w;
    }
    float d = den + 1e-8f;
    float4 o0, o1;
    o0.x = acc[0] / d; o0.y = acc[1] / d; o0.z = acc[2] / d; o0.w = acc[3] / d;
    o1.x = acc[4] / d; o1.y = acc[5] / d; o1.z = acc[6] / d; o1.w = acc[7] / d;
    float4* op = (float4*)(out + ((size_t)(b * KC + k) * DD + d0));
    op[0] = o0; op[1] = o1;
}

// ---------------- launch ----------------
extern "C" void kernel_launch(void* const* d_in, const int* in_sizes, int n_in,
                              void* d_out, int out_size) {
    const float* X = (const float*)d_in[0];
    const float* sal = (const float*)d_in[1];
    const float* gum = (const float*)d_in[2];
    float* out = (float*)d_out;

    const int MERGED = BN * KC * DD;
    float* mask_out;
    if (out_size >= MERGED + BN * NT) {
        mask_out = out + MERGED;
    } else {
        cudaError_t e; void* p = nullptr;
        e = cudaGetSymbolAddress(&p, g_maskdump);
        (void)e;
        mask_out = (float*)p;
    }

    const int NF4 = BN * NT * NT / 4;

    rnorm_kernel<<<BN * NT / 8, 256>>>(X);                  // 1
    mask_kernel<<<BN, 256>>>(sal, gum, mask_out);           // 2
    dummy_kernel<<<1, 32>>>();                              // 3
    gemm128<0, 4><<<dim3(3, BN, 4), 256>>>(X);              // 4 <- profiled slot
    combine0_kernel<<<NF4 / 256, 256>>>();                  // 5 (fused sqrow)
    gemm128<1, 2><<<dim3(3, BN, 2), 256>>>(nullptr);        // 6
    combine1_kernel<<<NF4 / 256, 256>>>();                  // 7
    cluster_kernel<<<BN / 2, 512>>>();                      // 8
    merge_kernel<<<BN * KC, 256>>>(X, out);                 // 9
}

// round 17
// speedup vs baseline: 1.1175x; 1.1175x over previous
#include <cuda_runtime.h>
#include <cstdint>
#include <cstddef>

#define BN 32
#define NT 256
#define DD 2048
#define KC 64
#define BIGF 1e30f

// ---------------- scratch (static device globals; no allocation) ----------------
__device__ float g_rinv[BN * NT];
__device__ float g_S[BN * NT * NT];              // 8.4 MB
__device__ float g_Dm[BN * NT * NT];             // 8.4 MB
__device__ float g_part[4][BN * NT * NT];        // 33.6 MB split-K partials
__device__ float g_sq[BN * NT];
__device__ float g_salmass[BN * NT];
__device__ float g_minv0[BN * NT];
__device__ int   g_mini0[BN * NT];
__device__ int   g_order[BN * NT];
__device__ int   g_ccnt[BN * KC];
__device__ int   g_coff[BN * KC];
__device__ float g_maskdump[BN * NT];

// ---------------- 1: reciprocal row norms ----------------
__global__ void rnorm_kernel(const float* __restrict__ X) {
    int row = blockIdx.x * 8 + (threadIdx.x >> 5);
    int lane = threadIdx.x & 31;
    const float* x = X + (size_t)row * DD;
    float s = 0.f;
    for (int c = lane * 4; c < DD; c += 128) {
        float4 v = *(const float4*)&x[c];
        s += v.x * v.x + v.y * v.y + v.z * v.z + v.w * v.w;
    }
    #pragma unroll
    for (int o = 16; o; o >>= 1) s += __shfl_down_sync(0xffffffffu, s, o);
    if (lane == 0) g_rinv[row] = 1.0f / fmaxf(sqrtf(s), 1e-12f);
}

__global__ void dummy_kernel() {}

// ---------------- 2: split-K fp32 GEMM with packed f32x2 FMA (proven 256-thread) ----------------
template <int MODE, int SPLIT>
__global__ __launch_bounds__(256, 2) void gemm128(const float* __restrict__ Ain) {
    constexpr int LD = (MODE == 0) ? DD : NT;
    constexpr int KP = LD / SPLIT;
    int b = blockIdx.y;
    int t3 = blockIdx.x;
    int tr = (t3 == 2) ? 1 : 0;
    int tc = (t3 == 0) ? 0 : 1;
    int koff = blockIdx.z * KP;
    const float* A = ((MODE == 0) ? Ain : g_S) + (size_t)b * NT * LD;
    float* P = g_part[blockIdx.z] + (size_t)b * NT * NT;

    __shared__ __align__(16) float As[2][8][132];
    __shared__ __align__(16) float Bs[2][8][132];

    int tid = threadIdx.x;
    int frow = tid & 127;
    int fk = (tid >> 7) * 4;
    int g = tid & 15;
    int h = tid >> 4;

    float sa = 1.f, sb = 1.f;
    if (MODE == 0) {
        sa = g_rinv[b * NT + tr * 128 + frow];
        sb = g_rinv[b * NT + tc * 128 + frow];
    }

    unsigned long long accd[8][4];
    #pragma unroll
    for (int i = 0; i < 8; i++)
        #pragma unroll
        for (int jp = 0; jp < 4; jp++) accd[i][jp] = 0ULL;

    const float* Ag = A + (size_t)(tr * 128 + frow) * LD + koff;
    const float* Bg = A + (size_t)(tc * 128 + frow) * LD + koff;

    {
        float4 fa = *(const float4*)(Ag + fk);
        float4 fb = *(const float4*)(Bg + fk);
        if (MODE == 0) {
            fa.x *= sa; fa.y *= sa; fa.z *= sa; fa.w *= sa;
            fb.x *= sb; fb.y *= sb; fb.z *= sb; fb.w *= sb;
        }
        As[0][fk + 0][frow] = fa.x; As[0][fk + 1][frow] = fa.y;
        As[0][fk + 2][frow] = fa.z; As[0][fk + 3][frow] = fa.w;
        Bs[0][fk + 0][frow] = fb.x; Bs[0][fk + 1][frow] = fb.y;
        Bs[0][fk + 2][frow] = fb.z; Bs[0][fk + 3][frow] = fb.w;
    }
    __syncthreads();

    int cur = 0;
    for (int k0 = 8; k0 < KP + 8; k0 += 8) {
        bool has = (k0 < KP);
        float4 na, nb;
        if (has) {
            na = *(const float4*)(Ag + k0 + fk);
            nb = *(const float4*)(Bg + k0 + fk);
            if (MODE == 0) {
                na.x *= sa; na.y *= sa; na.z *= sa; na.w *= sa;
                nb.x *= sb; nb.y *= sb; nb.z *= sb; nb.w *= sb;
            }
        }
        #pragma unroll
        for (int kk = 0; kk < 8; kk++) {
            float a4[8];
            *(float4*)&a4[0] = *(const float4*)&As[cur][kk][g * 4];
            *(float4*)&a4[4] = *(const float4*)&As[cur][kk][64 + g * 4];
            ulonglong2 b01 = *(const ulonglong2*)&Bs[cur][kk][h * 4];
            ulonglong2 b23 = *(const ulonglong2*)&Bs[cur][kk][64 + h * 4];
            unsigned long long bq0 = b01.x, bq1 = b01.y, bq2 = b23.x, bq3 = b23.y;
            #pragma unroll
            for (int i = 0; i < 8; i++) {
                unsigned int au = __float_as_uint(a4[i]);
                unsigned long long ad;
                asm("mov.b64 %0, {%1, %1};" : "=l"(ad) : "r"(au));
                asm("fma.rn.f32x2 %0, %1, %2, %0;" : "+l"(accd[i][0]) : "l"(ad), "l"(bq0));
                asm("fma.rn.f32x2 %0, %1, %2, %0;" : "+l"(accd[i][1]) : "l"(ad), "l"(bq1));
                asm("fma.rn.f32x2 %0, %1, %2, %0;" : "+l"(accd[i][2]) : "l"(ad), "l"(bq2));
                asm("fma.rn.f32x2 %0, %1, %2, %0;" : "+l"(accd[i][3]) : "l"(ad), "l"(bq3));
            }
        }
        if (has) {
            int alt = cur ^ 1;
            As[alt][fk + 0][frow] = na.x; As[alt][fk + 1][frow] = na.y;
            As[alt][fk + 2][frow] = na.z; As[alt][fk + 3][frow] = na.w;
            Bs[alt][fk + 0][frow] = nb.x; Bs[alt][fk + 1][frow] = nb.y;
            Bs[alt][fk + 2][frow] = nb.z; Bs[alt][fk + 3][frow] = nb.w;
            __syncthreads();
            cur = alt;
        }
    }

    int r0 = tr * 128, c0 = tc * 128;
    #pragma unroll
    for (int i = 0; i < 8; i++) {
        int r = r0 + ((i < 4) ? (g * 4 + i) : (64 + g * 4 + i - 4));
        float vv[8];
        #pragma unroll
        for (int jp = 0; jp < 4; jp++) {
            unsigned int lo, hi;
            asm("mov.b64 {%0, %1}, %2;" : "=r"(lo), "=r"(hi) : "l"(accd[i][jp]));
            vv[2 * jp]     = __uint_as_float(lo);
            vv[2 * jp + 1] = __uint_as_float(hi);
        }
        float4 v0 = {vv[0], vv[1], vv[2], vv[3]};
        float4 v1 = {vv[4], vv[5], vv[6], vv[7]};
        *(float4*)&P[r * NT + c0 + h * 4] = v0;
        *(float4*)&P[r * NT + c0 + 64 + h * 4] = v1;
        if (tr != tc) {
            #pragma unroll
            for (int j = 0; j < 4; j++) P[(c0 + h * 4 + j) * NT + r] = vv[j];
            #pragma unroll
            for (int j = 0; j < 4; j++) P[(c0 + 64 + h * 4 + j) * NT + r] = vv[4 + j];
        }
    }
}

// ---------------- combine0 + fused row sums of squares ----------------
__global__ __launch_bounds__(256) void combine0_kernel() {
    int tid = threadIdx.x;
    int idx = blockIdx.x * 256 + tid;
    const float4* p0 = (const float4*)g_part[0];
    const float4* p1 = (const float4*)g_part[1];
    const float4* p2 = (const float4*)g_part[2];
    const float4* p3 = (const float4*)g_part[3];
    float4 a = p0[idx], b = p1[idx], c = p2[idx], d = p3[idx];
    float4 o;
    o.x = ((a.x + b.x) + c.x) + d.x;
    o.y = ((a.y + b.y) + c.y) + d.y;
    o.z = ((a.z + b.z) + c.z) + d.z;
    o.w = ((a.w + b.w) + c.w) + d.w;
    ((float4*)g_S)[idx] = o;

    float s = o.x * o.x + o.y * o.y + o.z * o.z + o.w * o.w;
    #pragma unroll
    for (int off = 16; off; off >>= 1) s += __shfl_down_sync(0xffffffffu, s, off);
    __shared__ float sws[8];
    int wid = tid >> 5;
    if ((tid & 31) == 0) sws[wid] = s;
    __syncthreads();
    if (tid < 4) g_sq[blockIdx.x * 4 + tid] = sws[2 * tid] + sws[2 * tid + 1];
}

// Dm full-square write + per-row initial nearest neighbor (min, argmin)
__global__ __launch_bounds__(256) void combine1_kernel() {
    int tid = threadIdx.x;
    int idx = blockIdx.x * 256 + tid;
    int c4 = idx & 63;
    int r = (idx >> 6) & 255;
    int b = idx >> 14;
    const float4* p0 = (const float4*)g_part[0];
    const float4* p1 = (const float4*)g_part[1];
    float4 t0 = p0[idx], t1 = p1[idx];
    float sqr = g_sq[b * NT + r];
    float4 sqc = ((const float4*)(g_sq + b * NT))[c4];
    float4 o;
    o.x = sqrtf(fmaxf(sqr + sqc.x - 2.f * (t0.x + t1.x), 0.f));
    o.y = sqrtf(fmaxf(sqr + sqc.y - 2.f * (t0.y + t1.y), 0.f));
    o.z = sqrtf(fmaxf(sqr + sqc.z - 2.f * (t0.z + t1.z), 0.f));
    o.w = sqrtf(fmaxf(sqr + sqc.w - 2.f * (t0.w + t1.w), 0.f));
    int cb = c4 * 4;
    if (r == cb + 0) o.x = BIGF;
    if (r == cb + 1) o.y = BIGF;
    if (r == cb + 2) o.z = BIGF;
    if (r == cb + 3) o.w = BIGF;
    ((float4*)g_Dm)[idx] = o;

    float v = o.x; int ci = cb;
    if (o.y < v) { v = o.y; ci = cb + 1; }
    if (o.z < v) { v = o.z; ci = cb + 2; }
    if (o.w < v) { v = o.w; ci = cb + 3; }
    unsigned uv = __reduce_min_sync(0xffffffffu, __float_as_uint(v));
    unsigned cand = (__float_as_uint(v) == uv) ? (unsigned)ci : 0x7FFFFFFFu;
    unsigned wmin = __reduce_min_sync(0xffffffffu, cand);
    __shared__ float swv[8];
    __shared__ int   swi[8];
    int wid = tid >> 5;
    if ((tid & 31) == 0) { swv[wid] = __uint_as_float(uv); swi[wid] = (int)wmin; }
    __syncthreads();
    if (tid < 4) {
        float bv = swv[2 * tid]; int bi = swi[2 * tid];
        float v1 = swv[2 * tid + 1]; int i1 = swi[2 * tid + 1];
        if (v1 < bv || (v1 == bv && i1 < bi)) { bv = v1; bi = i1; }
        int flat_row = blockIdx.x * 4 + tid;
        g_minv0[flat_row] = bv;
        g_mini0[flat_row] = bi;
    }
}

// ---------------- 4: clustering v4 + REDUX reduces (R14 base, fast-div probe) ----------------
__device__ __forceinline__ void row_scan4m(const float* __restrict__ row,
                                           const unsigned int* __restrict__ actw,
                                           int lane, float& bv, int& bi) {
    const float4* r4 = (const float4*)row;
    float4 f0 = r4[lane];
    float4 f1 = r4[lane + 32];
    unsigned int w0 = actw[lane >> 3] >> ((4 * lane) & 31);
    unsigned int w1 = actw[(lane >> 3) + 4] >> ((4 * lane) & 31);
    float v = BIGF; int idx = 1 << 20;
    if ((w0 & 1u) && f0.x < v) { v = f0.x; idx = 4 * lane; }
    if ((w0 & 2u) && f0.y < v) { v = f0.y; idx = 4 * lane + 1; }
    if ((w0 & 4u) && f0.z < v) { v = f0.z; idx = 4 * lane + 2; }
    if ((w0 & 8u) && f0.w < v) { v = f0.w; idx = 4 * lane + 3; }
    if ((w1 & 1u) && f1.x < v) { v = f1.x; idx = 128 + 4 * lane; }
    if ((w1 & 2u) && f1.y < v) { v = f1.y; idx = 128 + 4 * lane + 1; }
    if ((w1 & 4u) && f1.z < v) { v = f1.z; idx = 128 + 4 * lane + 2; }
    if ((w1 & 8u) && f1.w < v) { v = f1.w; idx = 128 + 4 * lane + 3; }
    unsigned uv = __reduce_min_sync(0xffffffffu, __float_as_uint(v));
    unsigned cand = (__float_as_uint(v) == uv) ? (unsigned)idx : 0x7FFFFFFFu;
    bi = (int)__reduce_min_sync(0xffffffffu, cand);
    bv = __uint_as_float(uv);
}

__global__ __launch_bounds__(256) void cluster_kernel() {
    const int b = blockIdx.x;
    float* Dm = g_Dm + (size_t)b * NT * NT;
    const int t = threadIdx.x;
    const int lane = t & 31, wid = t >> 5;

    __shared__ __align__(16) float s_minv[2][NT];
    __shared__ short s_mini[NT];
    __shared__ float s_size[NT];
    __shared__ unsigned char s_active[NT];
    __shared__ unsigned int s_actw[8];
    __shared__ short s_label[NT];
    __shared__ float s_wv[8];
    __shared__ int   s_wi[8];
    __shared__ int   s_recount[2];
    __shared__ short s_relist[2][NT];

    s_active[t] = 1; s_size[t] = 1.f; s_label[t] = (short)t;
    s_minv[0][t] = g_minv0[b * NT + t];
    s_mini[t] = (short)g_mini0[b * NT + t];
    if (t < 8) s_actw[t] = 0xFFFFFFFFu;
    if (t < 2) s_recount[t] = 0;
    __syncthreads();

    int cur = 0;
    for (int it = 0; it < NT - KC; ++it) {
        int nxt = cur ^ 1;
        // ---- phase 1 (no internal barrier) ----
        int i;
        {
            const float4* m4 = (const float4*)s_minv[cur];
            float4 f0 = m4[lane];
            float4 f1 = m4[lane + 32];
            float v = f0.x; int idx = 4 * lane;
            if (f0.y < v) { v = f0.y; idx = 4 * lane + 1; }
            if (f0.z < v) { v = f0.z; idx = 4 * lane + 2; }
            if (f0.w < v) { v = f0.w; idx = 4 * lane + 3; }
            if (f1.x < v) { v = f1.x; idx = 128 + 4 * lane; }
            if (f1.y < v) { v = f1.y; idx = 128 + 4 * lane + 1; }
            if (f1.z < v) { v = f1.z; idx = 128 + 4 * lane + 2; }
            if (f1.w < v) { v = f1.w; idx = 128 + 4 * lane + 3; }
            unsigned uv = __reduce_min_sync(0xffffffffu, __float_as_uint(v));
            unsigned cand = (__float_as_uint(v) == uv) ? (unsigned)idx : 0x7FFFFFFFu;
            i = (int)__reduce_min_sync(0xffffffffu, cand);
        }
        int j = s_mini[i];
        float si = s_size[i], sj = s_size[j];
        bool act = (s_active[t] != 0);
        float nv = BIGF;
        if (act && t != j) {
            float di = Dm[(size_t)i * NT + t];
            float dj = Dm[(size_t)j * NT + t];
            nv = __fdividef(si * di + sj * dj, si + sj);
            if (t == i) nv = BIGF;
            Dm[(size_t)i * NT + t] = nv;
            Dm[(size_t)t * NT + i] = nv;
        }
        if (t == j) {
            s_active[j] = 0;
            s_actw[j >> 5] &= ~(1u << (j & 31));
        }
        if (s_label[t] == (short)j) s_label[t] = (short)i;

        // row i's new rowmin candidate from nv (REDUX lexicographic)
        {
            float cv = (act && t != i && t != j) ? nv : BIGF;
            unsigned uv2 = __reduce_min_sync(0xffffffffu, __float_as_uint(cv));
            unsigned cc = (__float_as_uint(cv) == uv2) ? (unsigned)t : 0x7FFFFFFFu;
            unsigned wmin = __reduce_min_sync(0xffffffffu, cc);
            if (lane == 0) { s_wv[wid] = __uint_as_float(uv2); s_wi[wid] = (int)wmin; }
        }

        // maintenance + copy-forward into s_minv[nxt]
        float nmv;
        if (!act || t == i || t == j) {
            nmv = BIGF;
        } else {
            float mv = s_minv[cur][t]; int mi = s_mini[t];
            if (mi == i || mi == j) {
                if (nv < mv) { nmv = nv; s_mini[t] = (short)i; }
                else { nmv = mv; int p = atomicAdd(&s_recount[cur], 1); s_relist[cur][p] = (short)t; }
            } else if (nv < mv || (nv == mv && i < mi)) {
                nmv = nv; s_mini[t] = (short)i;
            } else nmv = mv;
        }
        s_minv[nxt][t] = nmv;
        __syncthreads();                         // (B)

        // ---- phase 2 ----
        if (t == 0) {
            float bv = s_wv[0]; int bi2 = s_wi[0];
            #pragma unroll
            for (int w = 1; w < 8; w++)
                if (s_wv[w] < bv || (s_wv[w] == bv && s_wi[w] < bi2)) { bv = s_wv[w]; bi2 = s_wi[w]; }
            s_minv[nxt][i] = bv; s_mini[i] = (short)bi2;
            s_size[i] = si + sj;
            s_recount[nxt] = 0;
        }
        int rc = s_recount[cur];
        for (int e = wid; e < rc; e += 8) {
            int r2 = s_relist[cur][e];
            float v2; int i2;
            row_scan4m(Dm + (size_t)r2 * NT, s_actw, lane, v2, i2);
            if (lane == 0) { s_minv[nxt][r2] = v2; s_mini[r2] = (short)i2; }
        }
        __syncthreads();                         // (C)
        cur = nxt;
    }

    // canonical relabel: new_id = cumsum(active)-1
    __shared__ short s_newid[NT];
    __shared__ short s_flab[NT];
    __shared__ short s_cnt[KC];
    __shared__ short s_off[KC];
    {
        int c = 0;
        for (int r2 = 0; r2 <= t; ++r2) c += s_active[r2];
        s_newid[t] = (short)(c - 1);
    }
    __syncthreads();
    int fl = s_newid[s_label[t]];
    s_flab[t] = (short)fl;
    __syncthreads();
    if (t < KC) {
        int cnt = 0;
        for (int r2 = 0; r2 < NT; r2++) cnt += (s_flab[r2] == (short)t);
        s_cnt[t] = (short)cnt;
        g_ccnt[b * KC + t] = cnt;
    }
    __syncthreads();
    if (t < KC) {
        int off = 0;
        for (int k2 = 0; k2 < t; k2++) off += s_cnt[k2];
        s_off[t] = (short)off;
        g_coff[b * KC + t] = off;
    }
    __syncthreads();
    {
        int rank = 0;
        for (int r2 = 0; r2 < t; r2++) rank += (s_flab[r2] == (short)fl);
        g_order[b * NT + s_off[fl] + rank] = t;
    }
}

// ---------------- 5: mask (softmax) + sal_mass ----------------
__global__ void mask_kernel(const float* __restrict__ sal,
                            const float* __restrict__ gum,
                            float* __restrict__ mout) {
    int b = blockIdx.x, t = threadIdx.x;
    float s = sal[b * NT + t];
    float l = (s + gum[b * NT + t]) / 0.1f;
    __shared__ float red[8];
    float m = l;
    #pragma unroll
    for (int o = 16; o; o >>= 1) m = fmaxf(m, __shfl_xor_sync(0xffffffffu, m, o));
    if ((t & 31) == 0) red[t >> 5] = m;
    __syncthreads();
    float mx = red[0];
    #pragma unroll
    for (int w = 1; w < 8; w++) mx = fmaxf(mx, red[w]);
    float e = expf(l - mx);
    float sm = e;
    #pragma unroll
    for (int o = 16; o; o >>= 1) sm += __shfl_xor_sync(0xffffffffu, sm, o);
    __syncthreads();
    if ((t & 31) == 0) red[t >> 5] = sm;
    __syncthreads();
    float tot = 0.f;
    #pragma unroll
    for (int w = 0; w < 8; w++) tot += red[w];
    float mk = e / tot;
    mout[b * NT + t] = mk;
    g_salmass[b * NT + t] = mk * s + (1.f - mk) * 0.01f;
}

// ---------------- 6: saliency-weighted per-cluster merge ----------------
__global__ __launch_bounds__(256) void merge_kernel(const float* __restrict__ X,
                                                    float* __restrict__ out) {
    int b = blockIdx.x >> 6;
    int k = blockIdx.x & 63;
    int cnt = g_ccnt[b * KC + k];
    int off = g_coff[b * KC + k];
    int t = threadIdx.x;
    int d0 = t * 8;
    float acc[8] = {0.f, 0.f, 0.f, 0.f, 0.f, 0.f, 0.f, 0.f};
    float den = 0.f;
    for (int e = 0; e < cnt; ++e) {
        int tok = g_order[b * NT + off + e];
        float w = g_salmass[b * NT + tok];
        den += w;
        const float4* xp = (const float4*)(X + ((size_t)(b * NT + tok) * DD + d0));
        float4 x0 = xp[0], x1 = xp[1];
        acc[0] += w * x0.x; acc[1] += w * x0.y; acc[2] += w * x0.z; acc[3] += w * x0.w;
        acc[4] += w * x1.x; acc[5] += w * x1.y; acc[6] += w * x1.z; acc[7] += w * x1.w;
    }
    float d = den + 1e-8f;
    float4 o0, o1;
    o0.x = acc[0] / d; o0.y = acc[1] / d; o0.z = acc[2] / d; o0.w = acc[3] / d;
    o1.x = acc[4] / d; o1.y = acc[5] / d; o1.z = acc[6] / d; o1.w = acc[7] / d;
    float4* op = (float4*)(out + ((size_t)(b * KC + k) * DD + d0));
    op[0] = o0; op[1] = o1;
}

// ---------------- launch ----------------
extern "C" void kernel_launch(void* const* d_in, const int* in_sizes, int n_in,
                              void* d_out, int out_size) {
    const float* X = (const float*)d_in[0];
    const float* sal = (const float*)d_in[1];
    const float* gum = (const float*)d_in[2];
    float* out = (float*)d_out;

    const int MERGED = BN * KC * DD;
    float* mask_out;
    if (out_size >= MERGED + BN * NT) {
        mask_out = out + MERGED;
    } else {
        cudaError_t e; void* p = nullptr;
        e = cudaGetSymbolAddress(&p, g_maskdump);
        (void)e;
        mask_out = (float*)p;
    }

    const int NF4 = BN * NT * NT / 4;

    rnorm_kernel<<<BN * NT / 8, 256>>>(X);                  // 1
    mask_kernel<<<BN, 256>>>(sal, gum, mask_out);           // 2
    dummy_kernel<<<1, 32>>>();                              // 3
    gemm128<0, 4><<<dim3(3, BN, 4), 256>>>(X);              // 4 <- profiled slot
    combine0_kernel<<<NF4 / 256, 256>>>();                  // 5 (fused sqrow)
    gemm128<1, 2><<<dim3(3, BN, 2), 256>>>(nullptr);        // 6
    combine1_kernel<<<NF4 / 256, 256>>>();                  // 7
    cluster_kernel<<<BN, 256>>>();                          // 8
    merge_kernel<<<BN * KC, 256>>>(X, out);                 // 9
}